// round 1
// baseline (speedup 1.0000x reference)
#include <cuda_runtime.h>
#include <cstdint>
#include <math.h>

// Problem constants
#define BATCH  32
#define NFRM   512
#define DMODEL 512
#define HEADS  8
#define DEPTH  147
#define DH     (HEADS * DEPTH)     // 1176
#define MROWS  (BATCH * NFRM)      // 16384
#define QKCOLS (2 * DH)            // 2352

// Scratch (no allocations allowed — device globals)
__device__ float g_qk[(size_t)MROWS * QKCOLS];  // [16384, 2352]: q cols [0,1176), k cols [1176,2352)
__device__ float g_v [(size_t)MROWS * DH];      // [16384, 1176]

// ---------------------------------------------------------------------------
// Generic fp32 SGEMM: C[M,Nc] = A[M,K] * B[K,Nc] (+bias), all row-major.
// Tile: 128x64, K-step 8, 256 threads, 8x4 per-thread micro-tile.
// M must be a multiple of 128 and K a multiple of 8 (true for all our calls).
// Nc is guarded.
// ---------------------------------------------------------------------------
#define BM 128
#define BN 64
#define BK 8
#define TM 8
#define TN 4

__global__ __launch_bounds__(256) void sgemm_kernel(
    const float* __restrict__ A, int lda,
    const float* __restrict__ Bm, int ldb,
    float* __restrict__ C, int ldc,
    int Ncols, int K,
    const float* __restrict__ bias)
{
    __shared__ float As[BK][BM];
    __shared__ float Bs[BK][BN];

    const int tid = threadIdx.x;
    const int block_m = blockIdx.y * BM;
    const int block_n = blockIdx.x * BN;

    // A tile load mapping: each thread loads a float4 along K
    const int a_m = tid >> 1;             // 0..127
    const int a_k = (tid & 1) * 4;        // 0 or 4
    // B tile load mapping: each thread loads 2 floats along N
    const int b_k = tid >> 5;             // 0..7
    const int b_n = (tid & 31) * 2;       // 0..62

    const int tx = tid & 15;              // N-group
    const int ty = tid >> 4;              // M-group
    const int tm0 = ty * TM;
    const int tn0 = tx * TN;

    float acc[TM][TN];
    #pragma unroll
    for (int i = 0; i < TM; i++)
        #pragma unroll
        for (int j = 0; j < TN; j++) acc[i][j] = 0.0f;

    const float* Aptr = A + (size_t)(block_m + a_m) * lda + a_k;

    for (int k0 = 0; k0 < K; k0 += BK) {
        // Load A tile (128 x 8), transposed into As[k][m]
        float4 av = *reinterpret_cast<const float4*>(Aptr + k0);
        As[a_k + 0][a_m] = av.x;
        As[a_k + 1][a_m] = av.y;
        As[a_k + 2][a_m] = av.z;
        As[a_k + 3][a_m] = av.w;

        // Load B tile (8 x 64) with N guard
        {
            const int gn = block_n + b_n;
            float bx = 0.0f, by = 0.0f;
            if (gn < Ncols) {
                const float* bp = Bm + (size_t)(k0 + b_k) * ldb + gn;
                bx = bp[0];
                by = (gn + 1 < Ncols) ? bp[1] : 0.0f;
            }
            Bs[b_k][b_n]     = bx;
            Bs[b_k][b_n + 1] = by;
        }
        __syncthreads();

        #pragma unroll
        for (int kk = 0; kk < BK; kk++) {
            float4 a0 = *reinterpret_cast<const float4*>(&As[kk][tm0]);
            float4 a1 = *reinterpret_cast<const float4*>(&As[kk][tm0 + 4]);
            float4 b0 = *reinterpret_cast<const float4*>(&Bs[kk][tn0]);
            float ar[TM] = {a0.x, a0.y, a0.z, a0.w, a1.x, a1.y, a1.z, a1.w};
            float br[TN] = {b0.x, b0.y, b0.z, b0.w};
            #pragma unroll
            for (int i = 0; i < TM; i++)
                #pragma unroll
                for (int j = 0; j < TN; j++)
                    acc[i][j] = fmaf(ar[i], br[j], acc[i][j]);
        }
        __syncthreads();
    }

    // Store
    #pragma unroll
    for (int i = 0; i < TM; i++) {
        const int gm = block_m + tm0 + i;
        #pragma unroll
        for (int j = 0; j < TN; j++) {
            const int gn = block_n + tn0 + j;
            if (gn < Ncols) {
                float v = acc[i][j];
                if (bias) v += bias[gn];
                C[(size_t)gm * ldc + gn] = v;
            }
        }
    }
}

// ---------------------------------------------------------------------------
// Per-frame tiny attention. One warp per (b, n, h) frame; 8 warps per block.
// q/k read from g_qk; v updated in place in g_v (cols h*147+3 .. h*147+146).
// ---------------------------------------------------------------------------
__global__ __launch_bounds__(256) void attn_kernel(
    const float* __restrict__ qk, float* __restrict__ v)
{
    __shared__ float sm[8][1008];   // per warp: qa[144] ka[144] va[144] sc[576]

    const int warp = threadIdx.x >> 5;
    const int lane = threadIdx.x & 31;
    const int gw = blockIdx.x * 8 + warp;   // 0 .. 131071
    const int h  = gw & 7;
    const int bn = gw >> 3;

    float* qa = sm[warp];
    float* ka = qa + 144;
    float* va = ka + 144;
    float* sc = va + 144;

    const float* qrow = qk + (size_t)bn * QKCOLS + h * DEPTH + 3;
    const float* krow = qk + (size_t)bn * QKCOLS + DH + h * DEPTH + 3;
    float*       vrow = v  + (size_t)bn * DH + h * DEPTH + 3;

    for (int i = lane; i < 144; i += 32) {
        qa[i] = qrow[i];
        ka[i] = krow[i];
        va[i] = vrow[i];
    }
    __syncwarp();

    const float scale = 0.4082482904638631f;  // 1/sqrt(6)
    for (int idx = lane; idx < 576; idx += 32) {
        const int r = idx / 24;
        const int c = idx - r * 24;
        float s = 0.0f;
        #pragma unroll
        for (int d = 0; d < 6; d++) s = fmaf(qa[r * 6 + d], ka[c * 6 + d], s);
        sc[idx] = s * scale;
    }
    __syncwarp();

    if (lane < 24) {
        const int r = lane;
        float mx = -INFINITY;
        #pragma unroll
        for (int c = 0; c < 24; c++) mx = fmaxf(mx, sc[r * 24 + c]);
        float e[24];
        float sum = 0.0f;
        #pragma unroll
        for (int c = 0; c < 24; c++) { e[c] = __expf(sc[r * 24 + c] - mx); sum += e[c]; }
        const float inv = 1.0f / sum;
        #pragma unroll
        for (int c = 0; c < 24; c++) sc[r * 24 + c] = e[c] * inv;
    }
    __syncwarp();

    if (lane == 0) {
        #define P(r, c) sc[(r) * 24 + (c)]
        P(0, 6)  = (P(0, 6)  + P(0, 3))  * 0.5f;
        P(6, 0)  = (P(6, 0)  + P(3, 0))  * 0.5f;
        P(0, 9)  = (P(0, 9)  + P(0, 6))  * 0.5f;
        P(9, 0)  = (P(9, 0)  + P(6, 0))  * 0.5f;
        P(0, 12) = (P(0, 12) + P(0, 9))  * 0.5f;
        P(12, 0) = (P(12, 0) + P(9, 0))  * 0.5f;
        P(0, 13) = (P(0, 13) + P(0, 9))  * 0.5f;
        P(13, 0) = (P(13, 0) + P(9, 0))  * 0.5f;
        P(0, 14) = (P(0, 14) + P(0, 9))  * 0.5f;
        P(14, 0) = (P(14, 0) + P(9, 0))  * 0.5f;
        P(0, 16) = (P(0, 16) + P(0, 13)) * 0.5f;
        P(16, 0) = (P(16, 0) + P(13, 0)) * 0.5f;
        P(0, 17) = (P(0, 17) + P(0, 14)) * 0.5f;
        P(17, 0) = (P(17, 0) + P(14, 0)) * 0.5f;
        P(0, 15) = (P(0, 15) + P(0, 12)) * 0.5f;
        P(15, 0) = (P(15, 0) + P(12, 0)) * 0.5f;
        #undef P
    }
    __syncwarp();

    for (int idx = lane; idx < 144; idx += 32) {
        const int r = idx / 6;
        const int d = idx - r * 6;
        float s = 0.0f;
        #pragma unroll
        for (int c = 0; c < 24; c++) s = fmaf(sc[r * 24 + c], va[c * 6 + d], s);
        vrow[idx] = s;
    }
}

// ---------------------------------------------------------------------------
// Launch
// ---------------------------------------------------------------------------
extern "C" void kernel_launch(void* const* d_in, const int* in_sizes, int n_in,
                              void* d_out, int out_size)
{
    (void)in_sizes; (void)n_in; (void)out_size;
    const float* query = (const float*)d_in[0];
    // d_in[1] = key (unused by the reference model)
    const float* value = (const float*)d_in[2];
    const float* qk_w  = (const float*)d_in[3];
    const float* v_w   = (const float*)d_in[4];
    const float* lin_w = (const float*)d_in[5];
    const float* lin_b = (const float*)d_in[6];
    float* out = (float*)d_out;

    float* qk_buf = nullptr;
    float* v_buf  = nullptr;
    cudaGetSymbolAddress((void**)&qk_buf, g_qk);
    cudaGetSymbolAddress((void**)&v_buf,  g_v);

    dim3 block(256);

    // 1) combined_qk = query @ qk_w   -> g_qk [16384, 2352]
    {
        dim3 grid((QKCOLS + BN - 1) / BN, MROWS / BM);
        sgemm_kernel<<<grid, block>>>(query, DMODEL, qk_w, QKCOLS,
                                      qk_buf, QKCOLS, QKCOLS, DMODEL, nullptr);
    }
    // 2) v = value @ v_w              -> g_v [16384, 1176]
    {
        dim3 grid((DH + BN - 1) / BN, MROWS / BM);
        sgemm_kernel<<<grid, block>>>(value, DMODEL, v_w, DH,
                                      v_buf, DH, DH, DMODEL, nullptr);
    }
    // 3) per-frame attention, in-place update of g_v
    {
        dim3 grid((BATCH * NFRM * HEADS) / 8);   // 16384 blocks, 8 warps each
        attn_kernel<<<grid, block>>>(qk_buf, v_buf);
    }
    // 4) out = g_v @ lin_w + lin_b    -> [16384, 512]
    {
        dim3 grid(DMODEL / BN, MROWS / BM);
        sgemm_kernel<<<grid, block>>>(v_buf, DH, lin_w, DMODEL,
                                      out, DMODEL, DMODEL, DH, lin_b);
    }
}

// round 3
// speedup vs baseline: 1.9206x; 1.9206x over previous
#include <cuda_runtime.h>
#include <cuda_bf16.h>
#include <mma.h>
#include <cstdint>
#include <math.h>

using namespace nvcuda;

// ---------------------------------------------------------------------------
// Problem constants (padded so the GEMM mainloop needs no guards)
// ---------------------------------------------------------------------------
#define BATCH  32
#define NFRM   512
#define DMODEL 512
#define HEADS  8
#define DEPTH  147
#define DH     1176
#define MROWS  16384
#define QK_N   2352            // real qk columns (q:[0,1176), k:[1176,2352))
#define QK_NP  2432            // padded to 19*128
#define V_NP   1280            // padded DH to 10*128
#define K3P    1280            // padded K for gemm3 (40*32)

// ---------------------------------------------------------------------------
// Scratch (device globals; no runtime allocation allowed)
// ---------------------------------------------------------------------------
__device__ float g_qk[(size_t)MROWS * QK_NP];     // fp32 q|k (ld 2432)
__device__ float g_v [(size_t)MROWS * V_NP];      // fp32 v   (ld 1280)

__device__ __nv_bfloat16 g_a1h[(size_t)MROWS * DMODEL];
__device__ __nv_bfloat16 g_a1l[(size_t)MROWS * DMODEL];
__device__ __nv_bfloat16 g_a2h[(size_t)MROWS * DMODEL];
__device__ __nv_bfloat16 g_a2l[(size_t)MROWS * DMODEL];
__device__ __nv_bfloat16 g_a3h[(size_t)MROWS * K3P];
__device__ __nv_bfloat16 g_a3l[(size_t)MROWS * K3P];
__device__ __nv_bfloat16 g_b1h[(size_t)QK_NP * DMODEL];
__device__ __nv_bfloat16 g_b1l[(size_t)QK_NP * DMODEL];
__device__ __nv_bfloat16 g_b2h[(size_t)V_NP * DMODEL];
__device__ __nv_bfloat16 g_b2l[(size_t)V_NP * DMODEL];
__device__ __nv_bfloat16 g_b3h[(size_t)DMODEL * K3P];
__device__ __nv_bfloat16 g_b3l[(size_t)DMODEL * K3P];

// ---------------------------------------------------------------------------
// Helpers
// ---------------------------------------------------------------------------
__device__ __forceinline__ uint32_t smem_u32(const void* p) {
    uint32_t a;
    asm("{ .reg .u64 t; cvta.to.shared.u64 t, %1; cvt.u32.u64 %0, t; }" : "=r"(a) : "l"(p));
    return a;
}
__device__ __forceinline__ void cp16(void* dst, const void* src) {
    uint32_t s = smem_u32(dst);
    asm volatile("cp.async.cg.shared.global [%0], [%1], 16;" :: "r"(s), "l"(src) : "memory");
}
#define CP_COMMIT()  asm volatile("cp.async.commit_group;" ::: "memory")
#define CP_WAIT(n)   asm volatile("cp.async.wait_group %0;" :: "n"(n) : "memory")

// ---------------------------------------------------------------------------
// Split kernels: fp32 -> bf16 hi + lo (residual)
// ---------------------------------------------------------------------------
__global__ __launch_bounds__(256) void split_rm_kernel(
    const float* __restrict__ in, __nv_bfloat16* __restrict__ hi,
    __nv_bfloat16* __restrict__ lo, size_t n4)
{
    size_t i = (size_t)blockIdx.x * blockDim.x + threadIdx.x;
    size_t stride = (size_t)gridDim.x * blockDim.x;
    for (; i < n4; i += stride) {
        float4 v = reinterpret_cast<const float4*>(in)[i];
        float vv[4] = {v.x, v.y, v.z, v.w};
        __nv_bfloat16 h[4], l[4];
        #pragma unroll
        for (int j = 0; j < 4; j++) {
            h[j] = __float2bfloat16(vv[j]);
            l[j] = __float2bfloat16(vv[j] - __bfloat162float(h[j]));
        }
        reinterpret_cast<uint2*>(hi)[i] = *reinterpret_cast<uint2*>(h);
        reinterpret_cast<uint2*>(lo)[i] = *reinterpret_cast<uint2*>(l);
    }
}

// in [K][N] fp32 (row-major) -> out [NP][KP] bf16 hi/lo, zero-padded
__global__ __launch_bounds__(256) void split_tr_kernel(
    const float* __restrict__ in, __nv_bfloat16* __restrict__ hi,
    __nv_bfloat16* __restrict__ lo, int K, int N, int KP, int NP)
{
    __shared__ float tile[32][33];
    const int tx = threadIdx.x;       // 0..31
    const int ty = threadIdx.y;       // 0..7
    const int n0 = blockIdx.x * 32;
    const int k0 = blockIdx.y * 32;
    #pragma unroll
    for (int i = 0; i < 4; i++) {
        int k = k0 + ty + i * 8;
        int n = n0 + tx;
        tile[ty + i * 8][tx] = (k < K && n < N) ? in[(size_t)k * N + n] : 0.0f;
    }
    __syncthreads();
    #pragma unroll
    for (int i = 0; i < 4; i++) {
        int n = n0 + ty + i * 8;
        int k = k0 + tx;
        if (n < NP && k < KP) {
            float v = tile[tx][ty + i * 8];
            __nv_bfloat16 h = __float2bfloat16(v);
            __nv_bfloat16 l = __float2bfloat16(v - __bfloat162float(h));
            hi[(size_t)n * KP + k] = h;
            lo[(size_t)n * KP + k] = l;
        }
    }
}

// ---------------------------------------------------------------------------
// wmma bf16x3 GEMM: C[M,Np] = A*B^T over 3 K-segments (AhBh + AhBl + AlBh).
// A stored [M][ldA] bf16 (hi/lo), B stored [Np][ldB] bf16 (hi/lo).
// 256 threads, BM=128, BN=128, BK=32, cp.async double buffer, no guards.
// ---------------------------------------------------------------------------
#define BM 128
#define BN 128
#define BK 32
#define LDS 40                       // smem row pitch (elements), conflict-free

__global__ __launch_bounds__(256) void gemm_wmma_kernel(
    const __nv_bfloat16* __restrict__ Ah, const __nv_bfloat16* __restrict__ Al, int ldA,
    const __nv_bfloat16* __restrict__ Bh, const __nv_bfloat16* __restrict__ Bl, int ldB,
    float* __restrict__ C, int ldc, const float* __restrict__ bias, int SPS)
{
    // smem union: tiles (2 bufs x (A 128x40 + B 128x40) bf16 = 40960B)
    //             vs epilogue stage (128x68 f32 = 34816B)
    __shared__ __align__(16) char smem_raw[2 * (BM + BN) * LDS * 2];
    __nv_bfloat16* shA = reinterpret_cast<__nv_bfloat16*>(smem_raw);          // [2][BM*LDS]
    __nv_bfloat16* shB = shA + 2 * BM * LDS;                                  // [2][BN*LDS]

    const int tid  = threadIdx.x;
    const int warp = tid >> 5;
    const int wm   = warp & 3;         // 4 M-groups of 32
    const int wn   = warp >> 2;        // 2 N-groups of 64
    const int m0   = blockIdx.y * BM;
    const int n0   = blockIdx.x * BN;
    const int KT   = 3 * SPS;

    wmma::fragment<wmma::accumulator, 16, 16, 16, float> acc[2][4];
    #pragma unroll
    for (int i = 0; i < 2; i++)
        #pragma unroll
        for (int j = 0; j < 4; j++) wmma::fill_fragment(acc[i][j], 0.0f);

    auto issue = [&](int t, int buf) {
        const int seg = t / SPS;
        const int kk  = (t - seg * SPS) * BK;
        const __nv_bfloat16* Asrc = (seg < 2)  ? Ah : Al;
        const __nv_bfloat16* Bsrc = (seg == 1) ? Bl : Bh;
        __nv_bfloat16* dA = shA + buf * BM * LDS;
        __nv_bfloat16* dB = shB + buf * BN * LDS;
        #pragma unroll
        for (int i = 0; i < 2; i++) {
            int q = i * 256 + tid;           // 0..511
            int r = q >> 2, c = q & 3;       // row, 16B chunk
            cp16(dA + r * LDS + c * 8, Asrc + (size_t)(m0 + r) * ldA + kk + c * 8);
        }
        #pragma unroll
        for (int i = 0; i < 2; i++) {
            int q = i * 256 + tid;
            int r = q >> 2, c = q & 3;
            cp16(dB + r * LDS + c * 8, Bsrc + (size_t)(n0 + r) * ldB + kk + c * 8);
        }
        CP_COMMIT();
    };

    // prologue: stages 0 and 1 in flight
    issue(0, 0);
    issue(1, 1);
    CP_WAIT(1);
    __syncthreads();

    for (int t = 0; t < KT; t++) {
        const int buf = t & 1;
        const __nv_bfloat16* bA = shA + buf * BM * LDS;
        const __nv_bfloat16* bB = shB + buf * BN * LDS;

        #pragma unroll
        for (int ks = 0; ks < 2; ks++) {
            wmma::fragment<wmma::matrix_a, 16, 16, 16, __nv_bfloat16, wmma::row_major> fa[2];
            wmma::fragment<wmma::matrix_b, 16, 16, 16, __nv_bfloat16, wmma::col_major> fb[4];
            #pragma unroll
            for (int i = 0; i < 2; i++)
                wmma::load_matrix_sync(fa[i], bA + (wm * 32 + i * 16) * LDS + ks * 16, LDS);
            #pragma unroll
            for (int j = 0; j < 4; j++)
                wmma::load_matrix_sync(fb[j], bB + (wn * 64 + j * 16) * LDS + ks * 16, LDS);
            #pragma unroll
            for (int i = 0; i < 2; i++)
                #pragma unroll
                for (int j = 0; j < 4; j++)
                    wmma::mma_sync(acc[i][j], fa[i], fb[j], acc[i][j]);
        }
        __syncthreads();                       // everyone done reading buf

        if (t + 2 < KT) {
            issue(t + 2, buf);
            CP_WAIT(1);                        // stage t+1 landed
        } else if (t + 1 < KT) {
            CP_WAIT(0);
        }
        if (t + 1 < KT) __syncthreads();
    }

    // epilogue
    if (bias == nullptr) {
        #pragma unroll
        for (int i = 0; i < 2; i++)
            #pragma unroll
            for (int j = 0; j < 4; j++)
                wmma::store_matrix_sync(
                    C + (size_t)(m0 + wm * 32 + i * 16) * ldc + n0 + wn * 64 + j * 16,
                    acc[i][j], ldc, wmma::mem_row_major);
    } else {
        // stage through smem (ld 68) in two 64-col halves, add bias
        float* stage = reinterpret_cast<float*>(smem_raw);
        #pragma unroll
        for (int h = 0; h < 2; h++) {
            if (wn == h) {
                #pragma unroll
                for (int i = 0; i < 2; i++)
                    #pragma unroll
                    for (int j = 0; j < 4; j++)
                        wmma::store_matrix_sync(
                            stage + (wm * 32 + i * 16) * 68 + j * 16,
                            acc[i][j], 68, wmma::mem_row_major);
            }
            __syncthreads();
            #pragma unroll
            for (int r4 = 0; r4 < 8; r4++) {
                int idx = r4 * 256 + tid;      // 0..2047 float4s
                int row = idx >> 4;            // 0..127
                int c4  = idx & 15;            // 0..15
                float4 v = *reinterpret_cast<float4*>(stage + row * 68 + c4 * 4);
                int gn = n0 + h * 64 + c4 * 4;
                v.x += bias[gn + 0]; v.y += bias[gn + 1];
                v.z += bias[gn + 2]; v.w += bias[gn + 3];
                *reinterpret_cast<float4*>(C + (size_t)(m0 + row) * ldc + gn) = v;
            }
            __syncthreads();
        }
    }
}

// ---------------------------------------------------------------------------
// Per-frame tiny attention: 1 warp per (bn, h); lane r owns score row r (r<24).
// ---------------------------------------------------------------------------
__global__ __launch_bounds__(256) void attn_kernel(
    const float* __restrict__ qk, float* __restrict__ v)
{
    __shared__ float sm[8][432];   // per warp: qa[144] ka[144] va[144]

    const int warp = threadIdx.x >> 5;
    const int lane = threadIdx.x & 31;
    const int gw = blockIdx.x * 8 + warp;
    const int h  = gw & 7;
    const int bn = gw >> 3;

    float* qa = sm[warp];
    float* ka = qa + 144;
    float* va = ka + 144;

    const float* qrow = qk + (size_t)bn * QK_NP + h * DEPTH + 3;
    const float* krow = qk + (size_t)bn * QK_NP + DH + h * DEPTH + 3;
    float*       vrow = v  + (size_t)bn * V_NP + h * DEPTH + 3;

    for (int i = lane; i < 144; i += 32) {
        qa[i] = qrow[i];
        ka[i] = krow[i];
        va[i] = vrow[i];
    }
    __syncwarp();

    const float scale = 0.4082482904638631f;  // 1/sqrt(6)
    float p[24];
    #pragma unroll
    for (int c = 0; c < 24; c++) p[c] = 0.0f;

    if (lane < 24) {
        float qr[6];
        #pragma unroll
        for (int d = 0; d < 6; d++) qr[d] = qa[lane * 6 + d];
        #pragma unroll
        for (int c = 0; c < 24; c++) {
            const float2 k0 = *reinterpret_cast<const float2*>(ka + c * 6);
            const float2 k1 = *reinterpret_cast<const float2*>(ka + c * 6 + 2);
            const float2 k2 = *reinterpret_cast<const float2*>(ka + c * 6 + 4);
            float s = qr[0] * k0.x;
            s = fmaf(qr[1], k0.y, s);
            s = fmaf(qr[2], k1.x, s);
            s = fmaf(qr[3], k1.y, s);
            s = fmaf(qr[4], k2.x, s);
            s = fmaf(qr[5], k2.y, s);
            p[c] = s * scale;
        }
        float mx = p[0];
        #pragma unroll
        for (int c = 1; c < 24; c++) mx = fmaxf(mx, p[c]);
        float sum = 0.0f;
        #pragma unroll
        for (int c = 0; c < 24; c++) { p[c] = __expf(p[c] - mx); sum += p[c]; }
        const float inv = 1.0f / sum;
        #pragma unroll
        for (int c = 0; c < 24; c++) p[c] *= inv;
    }

    // Row-0 chain: lane 0's registers, exact reference order.
    if (lane == 0) {
        p[6]  = (p[6]  + p[3])  * 0.5f;
        p[9]  = (p[9]  + p[6])  * 0.5f;
        p[12] = (p[12] + p[9])  * 0.5f;
        p[13] = (p[13] + p[9])  * 0.5f;
        p[14] = (p[14] + p[9])  * 0.5f;
        p[16] = (p[16] + p[13]) * 0.5f;
        p[17] = (p[17] + p[14]) * 0.5f;
        p[15] = (p[15] + p[12]) * 0.5f;
    }
    // Column-0 chain: P(r,0) lives in lane r's p[0]; sequential via shuffles.
    {
        const unsigned FULL = 0xffffffffu;
        float c3 = __shfl_sync(FULL, p[0], 3);
        p[0] = (lane == 6) ? (p[0] + c3) * 0.5f : p[0];
        float c6 = __shfl_sync(FULL, p[0], 6);
        p[0] = (lane == 9) ? (p[0] + c6) * 0.5f : p[0];
        float c9 = __shfl_sync(FULL, p[0], 9);
        p[0] = (lane >= 12 && lane <= 14) ? (p[0] + c9) * 0.5f : p[0];
        float c12 = __shfl_sync(FULL, p[0], 12);
        float c13 = __shfl_sync(FULL, p[0], 13);
        float c14 = __shfl_sync(FULL, p[0], 14);
        p[0] = (lane == 16) ? (p[0] + c13) * 0.5f : p[0];
        p[0] = (lane == 17) ? (p[0] + c14) * 0.5f : p[0];
        p[0] = (lane == 15) ? (p[0] + c12) * 0.5f : p[0];
    }

    if (lane < 24) {
        float o0 = 0.f, o1 = 0.f, o2 = 0.f, o3 = 0.f, o4 = 0.f, o5 = 0.f;
        #pragma unroll
        for (int c = 0; c < 24; c++) {
            const float2 v0 = *reinterpret_cast<const float2*>(va + c * 6);
            const float2 v1 = *reinterpret_cast<const float2*>(va + c * 6 + 2);
            const float2 v2 = *reinterpret_cast<const float2*>(va + c * 6 + 4);
            o0 = fmaf(p[c], v0.x, o0);
            o1 = fmaf(p[c], v0.y, o1);
            o2 = fmaf(p[c], v1.x, o2);
            o3 = fmaf(p[c], v1.y, o3);
            o4 = fmaf(p[c], v2.x, o4);
            o5 = fmaf(p[c], v2.y, o5);
        }
        float* orow = vrow + lane * 6;
        orow[0] = o0; orow[1] = o1; orow[2] = o2;
        orow[3] = o3; orow[4] = o4; orow[5] = o5;
    }
}

// ---------------------------------------------------------------------------
// Launch
// ---------------------------------------------------------------------------
extern "C" void kernel_launch(void* const* d_in, const int* in_sizes, int n_in,
                              void* d_out, int out_size)
{
    (void)in_sizes; (void)n_in; (void)out_size;
    const float* query = (const float*)d_in[0];
    const float* value = (const float*)d_in[2];   // d_in[1] = key (unused by ref)
    const float* qk_w  = (const float*)d_in[3];
    const float* v_w   = (const float*)d_in[4];
    const float* lin_w = (const float*)d_in[5];
    const float* lin_b = (const float*)d_in[6];
    float* out = (float*)d_out;

    float *qk_buf, *v_buf;
    __nv_bfloat16 *a1h, *a1l, *a2h, *a2l, *a3h, *a3l;
    __nv_bfloat16 *b1h, *b1l, *b2h, *b2l, *b3h, *b3l;
    cudaGetSymbolAddress((void**)&qk_buf, g_qk);
    cudaGetSymbolAddress((void**)&v_buf,  g_v);
    cudaGetSymbolAddress((void**)&a1h, g_a1h); cudaGetSymbolAddress((void**)&a1l, g_a1l);
    cudaGetSymbolAddress((void**)&a2h, g_a2h); cudaGetSymbolAddress((void**)&a2l, g_a2l);
    cudaGetSymbolAddress((void**)&a3h, g_a3h); cudaGetSymbolAddress((void**)&a3l, g_a3l);
    cudaGetSymbolAddress((void**)&b1h, g_b1h); cudaGetSymbolAddress((void**)&b1l, g_b1l);
    cudaGetSymbolAddress((void**)&b2h, g_b2h); cudaGetSymbolAddress((void**)&b2l, g_b2l);
    cudaGetSymbolAddress((void**)&b3h, g_b3h); cudaGetSymbolAddress((void**)&b3l, g_b3l);

    dim3 trb(32, 8);

    // splits
    split_rm_kernel<<<1024, 256>>>(query, a1h, a1l, (size_t)MROWS * DMODEL / 4);
    split_rm_kernel<<<1024, 256>>>(value, a2h, a2l, (size_t)MROWS * DMODEL / 4);
    split_tr_kernel<<<dim3(QK_NP / 32, DMODEL / 32), trb>>>(qk_w,  b1h, b1l, DMODEL, QK_N, DMODEL, QK_NP);
    split_tr_kernel<<<dim3(V_NP / 32,  DMODEL / 32), trb>>>(v_w,   b2h, b2l, DMODEL, DH,   DMODEL, V_NP);
    split_tr_kernel<<<dim3(DMODEL / 32, K3P / 32),   trb>>>(lin_w, b3h, b3l, DH,     DMODEL, K3P, DMODEL);

    // gemm1: qk = query @ qk_w  -> g_qk [16384][2432], K=512 (SPS=16)
    gemm_wmma_kernel<<<dim3(QK_NP / BN, MROWS / BM), 256>>>(
        a1h, a1l, DMODEL, b1h, b1l, DMODEL, qk_buf, QK_NP, nullptr, DMODEL / BK);
    // gemm2: v = value @ v_w    -> g_v [16384][1280], K=512
    gemm_wmma_kernel<<<dim3(V_NP / BN, MROWS / BM), 256>>>(
        a2h, a2l, DMODEL, b2h, b2l, DMODEL, v_buf, V_NP, nullptr, DMODEL / BK);

    // attention (in-place on g_v)
    attn_kernel<<<(BATCH * NFRM * HEADS) / 8, 256>>>(qk_buf, v_buf);

    // split v (pad cols already zero) for gemm3
    split_rm_kernel<<<1024, 256>>>(v_buf, a3h, a3l, (size_t)MROWS * K3P / 4);

    // gemm3: out = v @ lin_w + lin_b -> [16384][512], K=1280 (SPS=40)
    gemm_wmma_kernel<<<dim3(DMODEL / BN, MROWS / BM), 256>>>(
        a3h, a3l, K3P, b3h, b3l, K3P, out, DMODEL, lin_b, K3P / BK);
}